// round 2
// baseline (speedup 1.0000x reference)
#include <cuda_runtime.h>

#define NTHREADS 256

typedef unsigned long long u64;

// ---- packed f32x2 helpers (sm_100+ paired-fp32 ops) ----
__device__ __forceinline__ u64 pk2(float lo, float hi){
    u64 r; asm("mov.b64 %0, {%1,%2};" : "=l"(r) : "f"(lo), "f"(hi)); return r;
}
__device__ __forceinline__ void up2(u64 v, float& lo, float& hi){
    asm("mov.b64 {%0,%1}, %2;" : "=f"(lo), "=f"(hi) : "l"(v));
}
__device__ __forceinline__ u64 sw2(u64 v){           // (lo,hi) -> (hi,lo)
    float a, b; up2(v, a, b); return pk2(b, a);
}
__device__ __forceinline__ u64 mul2(u64 a, u64 b){
    u64 d; asm("mul.rn.f32x2 %0, %1, %2;" : "=l"(d) : "l"(a), "l"(b)); return d;
}
__device__ __forceinline__ u64 fma2(u64 a, u64 b, u64 c){
    u64 d; asm("fma.rn.f32x2 %0, %1, %2, %3;" : "=l"(d) : "l"(a), "l"(b), "l"(c)); return d;
}

// cos/sin of half-angles of the 20 RX weights (computed once per launch)
__device__ float g_wc[20];
__device__ float g_ws[20];

__global__ void prep_kernel(const float* __restrict__ w){
    int i = threadIdx.x;
    if (i < 20){
        float t = 0.5f * w[i];
        g_wc[i] = cosf(t);
        g_ws[i] = sinf(t);
    }
}

__global__ void __launch_bounds__(NTHREADS)
qdqn_kernel(const float* __restrict__ x,
            const float* __restrict__ Wm,
            const float* __restrict__ bias,
            float* __restrict__ out,
            int Btot)
{
    int tid = blockIdx.x * NTHREADS + threadIdx.x;
    if (tid >= Btot) return;

    // ---- hoist the 20 weight-gate (cos,sin) pairs: issue loads back-to-back ----
    float wc[20], ws[20];
    #pragma unroll
    for (int i = 0; i < 20; i++){ wc[i] = g_wc[i]; ws[i] = g_ws[i]; }

    // ---- embedding angles: clip(x/bounds,-1,1)*pi ; we need half-angles ----
    float4 xv = reinterpret_cast<const float4*>(x)[tid];
    float xs[4] = {xv.x, xv.y, xv.z, xv.w};
    const float invb[4] = {1.0f/4.8f, 0.25f, 1.0f/0.418f, 0.25f};
    float cy[4], sy[4];
    #pragma unroll
    for (int q = 0; q < 4; q++){
        float t = xs[q] * invb[q];
        t = fminf(fmaxf(t, -1.0f), 1.0f);
        __sincosf(t * 1.57079632679f, &sy[q], &cy[q]);   // half-angle in [-pi/2, pi/2]
    }

    // state: 16 amplitudes, each packed (re, im) in 64 bits
    u64 p[16];

    // ---- layer 0 RYs on |0000>: real product state, 28 mults ----
    {
        float r01[4], r[16];
        r01[0] = cy[0]*cy[1]; r01[1] = cy[0]*sy[1];
        r01[2] = sy[0]*cy[1]; r01[3] = sy[0]*sy[1];
        #pragma unroll
        for (int a = 0; a < 4; a++){
            float r2c = r01[a]*cy[2], r2s = r01[a]*sy[2];
            r[a*4+0] = r2c*cy[3]; r[a*4+1] = r2c*sy[3];
            r[a*4+2] = r2s*cy[3]; r[a*4+3] = r2s*sy[3];
        }
        #pragma unroll
        for (int i = 0; i < 16; i++) p[i] = pk2(r[i], 0.0f);
    }

    // ---- 5 layers ----
    #pragma unroll
    for (int l = 0; l < 5; l++){
        // RY data re-uploading (layer 0 already folded into the init above)
        if (l > 0){
            #pragma unroll
            for (int q = 0; q < 4; q++){
                const int m = 8 >> q;                       // wire q = bit (3-q)
                u64 c2  = pk2( cy[q],  cy[q]);
                u64 s2  = pk2( sy[q],  sy[q]);
                u64 ns2 = pk2(-sy[q], -sy[q]);
                #pragma unroll
                for (int i = 0; i < 16; i++){
                    if (i & m) continue;
                    int j = i | m;
                    u64 a = p[i], b = p[j];
                    p[i] = fma2(ns2, b, mul2(c2, a));       // c*a - s*b
                    p[j] = fma2(s2,  a, mul2(c2, b));       // s*a + c*b
                }
            }
        }
        // RX entangler rotations: [[c, -i s],[-i s, c]]
        #pragma unroll
        for (int q = 0; q < 4; q++){
            const int m = 8 >> q;
            float cw  = wc[l*4 + q];
            float swv = ws[l*4 + q];
            u64 c2  = pk2(cw,  cw);
            u64 sn2 = pk2(swv, -swv);                       // (s, -s)
            #pragma unroll
            for (int i = 0; i < 16; i++){
                if (i & m) continue;
                int j = i | m;
                u64 a = p[i], b = p[j];
                // a' = (c*a.re + s*b.im, c*a.im - s*b.re)
                p[i] = fma2(sn2, sw2(b), mul2(c2, a));
                // b' = (c*b.re + s*a.im, c*b.im - s*a.re)
                p[j] = fma2(sn2, sw2(a), mul2(c2, b));
            }
        }
        // CNOT ring (0->1, 1->2, 2->3, 3->0): pure compile-time permutations
        #pragma unroll
        for (int q = 0; q < 4; q++){
            const int c = q, t = (q + 1) & 3;
            const int mc = 8 >> c, mt = 8 >> t;
            #pragma unroll
            for (int i = 0; i < 16; i++){
                if ((i & mc) && !(i & mt)){
                    u64 tmp = p[i]; p[i] = p[i | mt]; p[i | mt] = tmp;
                }
            }
        }
    }

    // ---- probabilities and <Z_q> ----
    float pr[16];
    #pragma unroll
    for (int i = 0; i < 16; i++){
        float re, im; up2(p[i], re, im);
        pr[i] = re*re + im*im;
    }
    float e[4];
    #pragma unroll
    for (int q = 0; q < 4; q++){
        const int m = 8 >> q;
        float s = 0.0f;
        #pragma unroll
        for (int i = 0; i < 16; i++) s += (i & m) ? -pr[i] : pr[i];
        e[q] = s;
    }

    // ---- linear head: out = e @ W.T + b ----
    float o0 = __ldg(bias + 0), o1 = __ldg(bias + 1);
    #pragma unroll
    for (int q = 0; q < 4; q++){
        o0 = fmaf(__ldg(Wm + q),     e[q], o0);
        o1 = fmaf(__ldg(Wm + 4 + q), e[q], o1);
    }
    reinterpret_cast<float2*>(out)[tid] = make_float2(o0, o1);
}

extern "C" void kernel_launch(void* const* d_in, const int* in_sizes, int n_in,
                              void* d_out, int out_size)
{
    const float* x  = (const float*)d_in[0];   // (B,4)
    const float* w  = (const float*)d_in[1];   // (5,4)
    const float* Wm = (const float*)d_in[2];   // (2,4)
    const float* b  = (const float*)d_in[3];   // (2,)
    int Btot = in_sizes[0] / 4;
    float* out = (float*)d_out;

    prep_kernel<<<1, 32>>>(w);
    qdqn_kernel<<<(Btot + NTHREADS - 1) / NTHREADS, NTHREADS>>>(x, Wm, b, out, Btot);
}